// round 14
// baseline (speedup 1.0000x reference)
#include <cuda_runtime.h>
#include <cuda_bf16.h>
#include <math.h>
#include <stdint.h>

#define Bb 128
#define Tt 128
#define Vv 10000
#define VvPad 10112          // 79*128
#define Ee 256
#define Hh 1024
#define Dd 128
#define G3 3072              // 3*H
#define MROWS (Bb*Tt)        // 16384
#define NKS 6                // GRU k-splits: 192,192,192,192,128,128
#define NNT 24               // GRU n-tiles of 128
#define GRID_GRU (NKS*NNT)   // 144 CTAs, all co-resident
#define EMB_JOBS (24*128)    // 3072 embed tile-jobs
#define W1_JOBS  (2*256)     // 512 w1 tile-jobs (64x64)
#define W2_JOBS  (79*128)    // 10112 w2 tile-jobs (128x128)

// ---------------- scratch (__device__ globals: allowed) --------------------
__device__ float g_xg[MROWS * G3];       // [T][B][3H] input-side preacts (incl bi)
__device__ float g_hs[MROWS * Hh];       // [T][B][H]
__device__ float g_rgp[NKS * Bb * G3];   // recurrent matmul partials per k-split
__device__ __nv_bfloat16 g_rkT_hi[G3 * Hh];  // rk^T split hi  [n][k]
__device__ __nv_bfloat16 g_rkT_lo[G3 * Hh];  // rk^T split lo
__device__ __nv_bfloat16 g_hhi[Bb * Hh];     // h_t split hi [b][k]
__device__ __nv_bfloat16 g_hlo[Bb * Hh];     // h_t split lo
__device__ __nv_bfloat16 g_w2T_hi[VvPad * Dd]; // w2^T split, zero-padded rows
__device__ __nv_bfloat16 g_w2T_lo[VvPad * Dd];
__device__ __nv_bfloat16 g_dhi[MROWS * Dd];  // d = relu(hs@w1+b1) split hi
__device__ __nv_bfloat16 g_dlo[MROWS * Dd];  // split lo
__device__ __nv_bfloat16 g_gkT_hi[G3 * Ee];  // gru_k^T split [n][k]
__device__ __nv_bfloat16 g_gkT_lo[G3 * Ee];
__device__ __nv_bfloat16 g_xhi[MROWS * Ee];  // x = emb[tokens] split
__device__ __nv_bfloat16 g_xlo[MROWS * Ee];
__device__ unsigned g_bar;

__global__ void k_reset() { g_bar = 0u; }

// ---------------- PTX helpers ----------------------------------------------
__device__ __forceinline__ uint32_t smem_to_u32(const void* p) {
    uint32_t a;
    asm("{ .reg .u64 t; cvta.to.shared.u64 t, %1; cvt.u32.u64 %0, t; }"
        : "=r"(a) : "l"(p));
    return a;
}
__device__ __forceinline__ void ldsm_x4(uint32_t* r, uint32_t addr) {
    asm volatile("ldmatrix.sync.aligned.m8n8.x4.shared.b16 {%0,%1,%2,%3}, [%4];"
        : "=r"(r[0]), "=r"(r[1]), "=r"(r[2]), "=r"(r[3]) : "r"(addr));
}
__device__ __forceinline__ void mma_16816(float* d, const uint32_t* a, const uint32_t* b) {
    asm volatile("mma.sync.aligned.m16n8k16.row.col.f32.bf16.bf16.f32 "
        "{%0,%1,%2,%3}, {%4,%5,%6,%7}, {%8,%9}, {%0,%1,%2,%3};"
        : "+f"(d[0]), "+f"(d[1]), "+f"(d[2]), "+f"(d[3])
        : "r"(a[0]), "r"(a[1]), "r"(a[2]), "r"(a[3]), "r"(b[0]), "r"(b[1]));
}
__device__ __forceinline__ void cp16(uint32_t dst, const void* src) {
    asm volatile("cp.async.cg.shared.global [%0], [%1], 16;" :: "r"(dst), "l"(src));
}
#define CP_COMMIT() asm volatile("cp.async.commit_group;" ::: "memory")
#define CP_WAIT(n)  asm volatile("cp.async.wait_group %0;" :: "n"(n) : "memory")

__device__ __forceinline__ float sig_(float x) { return 1.f / (1.f + expf(-x)); }

// SMEM tile geometry: 128 rows x 64 bf16, rows padded to 72 bf16 = 144 B
#define ROWB 144
#define TILEB 18432          // 128*144
#define BUFB  (4*TILEB)      // Ah, Al, Bh, Bl
#define GRU_SMEM (2*BUFB)    // double buffered = 147456 B

// ---------------------------------------------------------------------------
// init: split + transpose rk [K=1024][N=3072] -> rkT hi/lo [N=3072][K=1024]
// ---------------------------------------------------------------------------
__global__ __launch_bounds__(256) void k_rk_split(const float* __restrict__ rk)
{
    __shared__ float tile[32][33];
    const int n0 = blockIdx.x * 32, k0 = blockIdx.y * 32;
    const int tx = threadIdx.x & 31, ty = threadIdx.x >> 5;  // ty 0..7
#pragma unroll
    for (int i = 0; i < 4; i++)
        tile[ty + 8 * i][tx] = rk[(size_t)(k0 + ty + 8 * i) * G3 + n0 + tx];
    __syncthreads();
#pragma unroll
    for (int i = 0; i < 4; i++) {
        int n = n0 + ty + 8 * i;
        float v = tile[tx][ty + 8 * i];
        __nv_bfloat16 hi = __float2bfloat16(v);
        __nv_bfloat16 lo = __float2bfloat16(v - __bfloat162float(hi));
        g_rkT_hi[(size_t)n * Hh + k0 + tx] = hi;
        g_rkT_lo[(size_t)n * Hh + k0 + tx] = lo;
    }
}

// ---------------------------------------------------------------------------
// init: split + transpose gk [K=256][N=3072] -> gkT hi/lo [N=3072][K=256]
// ---------------------------------------------------------------------------
__global__ __launch_bounds__(256) void k_gksplit(const float* __restrict__ gk)
{
    __shared__ float tile[32][33];
    const int n0 = blockIdx.x * 32, k0 = blockIdx.y * 32;
    const int tx = threadIdx.x & 31, ty = threadIdx.x >> 5;
#pragma unroll
    for (int i = 0; i < 4; i++)
        tile[ty + 8 * i][tx] = gk[(size_t)(k0 + ty + 8 * i) * G3 + n0 + tx];
    __syncthreads();
#pragma unroll
    for (int i = 0; i < 4; i++) {
        int n = n0 + ty + 8 * i;
        float v = tile[tx][ty + 8 * i];
        __nv_bfloat16 hi = __float2bfloat16(v);
        __nv_bfloat16 lo = __float2bfloat16(v - __bfloat162float(hi));
        g_gkT_hi[(size_t)n * Ee + k0 + tx] = hi;
        g_gkT_lo[(size_t)n * Ee + k0 + tx] = lo;
    }
}

// ---------------------------------------------------------------------------
// init: gather + split x = emb[tokens]  (row r = t*B+b)
// ---------------------------------------------------------------------------
__global__ __launch_bounds__(256) void k_xsplit(
    const int* __restrict__ tokens, const float* __restrict__ emb)
{
    int idx = blockIdx.x * 256 + threadIdx.x;   // float4 index over MROWS*64
    int r = idx >> 6, c4 = idx & 63;
    int tok = tokens[(r & 127) * Tt + (r >> 7)];
    float4 v = reinterpret_cast<const float4*>(emb)[(size_t)tok * 64 + c4];
    union { __nv_bfloat16 bf[4]; uint2 u; } ph, pl;
    ph.bf[0] = __float2bfloat16(v.x); ph.bf[1] = __float2bfloat16(v.y);
    ph.bf[2] = __float2bfloat16(v.z); ph.bf[3] = __float2bfloat16(v.w);
    pl.bf[0] = __float2bfloat16(v.x - __bfloat162float(ph.bf[0]));
    pl.bf[1] = __float2bfloat16(v.y - __bfloat162float(ph.bf[1]));
    pl.bf[2] = __float2bfloat16(v.z - __bfloat162float(ph.bf[2]));
    pl.bf[3] = __float2bfloat16(v.w - __bfloat162float(ph.bf[3]));
    *(uint2*)(g_xhi + (size_t)r * Ee + c4 * 4) = ph.u;
    *(uint2*)(g_xlo + (size_t)r * Ee + c4 * 4) = pl.u;
}

// ---------------------------------------------------------------------------
// init: split + transpose w2 [Dd=128][Vv] -> w2T hi/lo [VvPad][Dd], zero-pad
// ---------------------------------------------------------------------------
__global__ __launch_bounds__(256) void k_w2split(const float* __restrict__ w2)
{
    __shared__ float tile[32][33];
    const int n0 = blockIdx.x * 32, k0 = blockIdx.y * 32;
    const int tx = threadIdx.x & 31, ty = threadIdx.x >> 5;
#pragma unroll
    for (int i = 0; i < 4; i++) {
        int c = n0 + tx;
        tile[ty + 8 * i][tx] =
            (c < Vv) ? w2[(size_t)(k0 + ty + 8 * i) * Vv + c] : 0.f;
    }
    __syncthreads();
#pragma unroll
    for (int i = 0; i < 4; i++) {
        int n = n0 + ty + 8 * i;
        float v = tile[tx][ty + 8 * i];
        __nv_bfloat16 hi = __float2bfloat16(v);
        __nv_bfloat16 lo = __float2bfloat16(v - __bfloat162float(hi));
        g_w2T_hi[(size_t)n * Dd + k0 + tx] = hi;
        g_w2T_lo[(size_t)n * Dd + k0 + tx] = lo;
    }
}

// ---------------------------------------------------------------------------
// Persistent mega-kernel:
//   embed pre-phase (mma job loop)  -> barrier
//   GRU time loop (phase A mma + phase B gates, barrier x2/step)
//   w1 fp32 job loop -> barrier
//   w2 mma job loop -> done
// ---------------------------------------------------------------------------
__global__ __launch_bounds__(256, 1) void k_gru_mma(
    const float* __restrict__ br, const float* __restrict__ bi,
    const float* __restrict__ w1, const float* __restrict__ b1,
    const float* __restrict__ b2, float* __restrict__ out)
{
    extern __shared__ char smem[];
    __shared__ float W1As[16][68];
    __shared__ float W1Bs[16][68];
    const uint32_t sb = smem_to_u32(smem);
    const int tid = threadIdx.x;
    const int lane = tid & 31;
    const int wid = tid >> 5;
    const int ntile = blockIdx.x % NNT;
    const int ks    = blockIdx.x / NNT;      // 0..5
    const int n0    = ntile * 128;
    const int kbase = (ks < 4) ? ks * 192 : 768 + (ks - 4) * 128;
    const int nch   = (ks < 4) ? 3 : 2;      // chunks of 64 k
    const int mbase = (wid & 3) * 32;        // warp M rows (batch)
    const int nbase = (wid >> 2) * 64;       // warp N cols within tile

    const int lrow = tid >> 3;
    const int lg   = tid & 7;
    const uint32_t aoff = (uint32_t)((lane & 15) * ROWB + ((lane >> 4) & 1) * 16);
    const uint32_t boff = (uint32_t)((((lane & 7) + ((lane >> 4) & 1) * 8)) * ROWB
                                     + ((lane >> 3) & 1) * 16);

    unsigned epoch = 0;

    // ================= embed pre-phase: xg = x @ gkT + bi =================
    for (int job = blockIdx.x; job < EMB_JOBS; job += GRID_GRU) {
        const int em0 = (job & 127) * 128;   // m-tile
        const int en0 = (job >> 7) * 128;    // n-tile (0..23)

        float accs[64];
#pragma unroll
        for (int i = 0; i < 64; i++) accs[i] = 0.f;

#pragma unroll
        for (int c = 0; c < 2; c++) {
            const int kcur = c * 64;
            const uint32_t base = sb + c * BUFB;
#pragma unroll
            for (int i = 0; i < 4; i++) {
                const int row = lrow + 32 * i;
                const uint32_t d = base + row * ROWB + lg * 16;
                const size_t ea = ((size_t)(em0 + row) * Ee + kcur + lg * 8) * 2;
                cp16(d,             (const char*)g_xhi + ea);
                cp16(d + TILEB,     (const char*)g_xlo + ea);
                const size_t eb = ((size_t)(en0 + row) * Ee + kcur + lg * 8) * 2;
                cp16(d + 2 * TILEB, (const char*)g_gkT_hi + eb);
                cp16(d + 3 * TILEB, (const char*)g_gkT_lo + eb);
            }
            CP_COMMIT();
        }

        for (int c = 0; c < 4; c++) {
            if (c < 3) { CP_WAIT(1); } else { CP_WAIT(0); }
            __syncthreads();
            const uint32_t bufA = sb + (c & 1) * BUFB;
#pragma unroll
            for (int k = 0; k < 4; k++) {
                uint32_t ah[2][4], al[2][4];
#pragma unroll
                for (int mf = 0; mf < 2; mf++) {
                    const uint32_t ad = bufA + (mbase + mf * 16) * ROWB + k * 32 + aoff;
                    ldsm_x4(ah[mf], ad);
                    ldsm_x4(al[mf], ad + TILEB);
                }
#pragma unroll
                for (int nl = 0; nl < 4; nl++) {
                    const uint32_t bd = bufA + 2 * TILEB
                                      + (nbase + nl * 16) * ROWB + k * 32 + boff;
                    uint32_t bh[4], bl[4];
                    ldsm_x4(bh, bd);
                    ldsm_x4(bl, bd + TILEB);
#pragma unroll
                    for (int mf = 0; mf < 2; mf++) {
#pragma unroll
                        for (int h2 = 0; h2 < 2; h2++) {
                            float* a = &accs[(mf * 8 + nl * 2 + h2) * 4];
                            mma_16816(a, ah[mf], &bh[2 * h2]);
                            mma_16816(a, ah[mf], &bl[2 * h2]);
                            mma_16816(a, al[mf], &bh[2 * h2]);
                        }
                    }
                }
            }
            __syncthreads();
            if (c + 2 < 4) {
                const int cc = c + 2;
                const int kcur = cc * 64;
                const uint32_t base = sb + (cc & 1) * BUFB;
#pragma unroll
                for (int i = 0; i < 4; i++) {
                    const int row = lrow + 32 * i;
                    const uint32_t d = base + row * ROWB + lg * 16;
                    const size_t ea = ((size_t)(em0 + row) * Ee + kcur + lg * 8) * 2;
                    cp16(d,             (const char*)g_xhi + ea);
                    cp16(d + TILEB,     (const char*)g_xlo + ea);
                    const size_t eb = ((size_t)(en0 + row) * Ee + kcur + lg * 8) * 2;
                    cp16(d + 2 * TILEB, (const char*)g_gkT_hi + eb);
                    cp16(d + 3 * TILEB, (const char*)g_gkT_lo + eb);
                }
                CP_COMMIT();
            }
        }

#pragma unroll
        for (int mf = 0; mf < 2; mf++) {
#pragma unroll
            for (int nf = 0; nf < 8; nf++) {
                const float* a = &accs[(mf * 8 + nf) * 4];
                const int col = en0 + nbase + (nf >> 1) * 16 + (nf & 1) * 8 + (lane & 3) * 2;
                float2 bv = *(const float2*)(bi + col);
#pragma unroll
                for (int half = 0; half < 2; half++) {
                    const int r = em0 + mbase + mf * 16 + (lane >> 2) + half * 8;
                    *(float2*)(g_xg + (size_t)r * G3 + col) =
                        make_float2(a[2 * half + 0] + bv.x, a[2 * half + 1] + bv.y);
                }
            }
        }
    }
    // grid barrier
    __syncthreads();
    if (tid == 0) {
        __threadfence();
        epoch++;
        atomicAdd(&g_bar, 1u);
        while (*(volatile unsigned*)&g_bar < epoch * GRID_GRU) { }
    }
    __syncthreads();

    // ================= GRU time loop =================
    for (int t = 0; t < Tt; t++) {
        if (t > 0) {
            float accs[64];
#pragma unroll
            for (int i = 0; i < 64; i++) accs[i] = 0.f;

#pragma unroll
            for (int c = 0; c < 2; c++) {
                const int kcur = kbase + c * 64;
                const uint32_t base = sb + c * BUFB;
#pragma unroll
                for (int i = 0; i < 4; i++) {
                    const int row = lrow + 32 * i;
                    const uint32_t d = base + row * ROWB + lg * 16;
                    const size_t ea = ((size_t)row * Hh + kcur + lg * 8) * 2;
                    cp16(d,             (const char*)g_hhi + ea);
                    cp16(d + TILEB,     (const char*)g_hlo + ea);
                    const size_t eb = ((size_t)(n0 + row) * Hh + kcur + lg * 8) * 2;
                    cp16(d + 2 * TILEB, (const char*)g_rkT_hi + eb);
                    cp16(d + 3 * TILEB, (const char*)g_rkT_lo + eb);
                }
                CP_COMMIT();
            }

            for (int c = 0; c < nch; c++) {
                if (c < nch - 1) { CP_WAIT(1); } else { CP_WAIT(0); }
                __syncthreads();
                const uint32_t bufA = sb + (c & 1) * BUFB;
#pragma unroll
                for (int k = 0; k < 4; k++) {
                    uint32_t ah[2][4], al[2][4];
#pragma unroll
                    for (int mf = 0; mf < 2; mf++) {
                        const uint32_t ad = bufA + (mbase + mf * 16) * ROWB + k * 32 + aoff;
                        ldsm_x4(ah[mf], ad);
                        ldsm_x4(al[mf], ad + TILEB);
                    }
#pragma unroll
                    for (int nl = 0; nl < 4; nl++) {
                        const uint32_t bd = bufA + 2 * TILEB
                                          + (nbase + nl * 16) * ROWB + k * 32 + boff;
                        uint32_t bh[4], bl[4];
                        ldsm_x4(bh, bd);
                        ldsm_x4(bl, bd + TILEB);
#pragma unroll
                        for (int mf = 0; mf < 2; mf++) {
#pragma unroll
                            for (int h2 = 0; h2 < 2; h2++) {
                                float* a = &accs[(mf * 8 + nl * 2 + h2) * 4];
                                mma_16816(a, ah[mf], &bh[2 * h2]);
                                mma_16816(a, ah[mf], &bl[2 * h2]);
                                mma_16816(a, al[mf], &bh[2 * h2]);
                            }
                        }
                    }
                }
                __syncthreads();
                if (c + 2 < nch) {
                    const int cc = c + 2;
                    const int kcur = kbase + cc * 64;
                    const uint32_t base = sb + (cc & 1) * BUFB;
#pragma unroll
                    for (int i = 0; i < 4; i++) {
                        const int row = lrow + 32 * i;
                        const uint32_t d = base + row * ROWB + lg * 16;
                        const size_t ea = ((size_t)row * Hh + kcur + lg * 8) * 2;
                        cp16(d,             (const char*)g_hhi + ea);
                        cp16(d + TILEB,     (const char*)g_hlo + ea);
                        const size_t eb = ((size_t)(n0 + row) * Hh + kcur + lg * 8) * 2;
                        cp16(d + 2 * TILEB, (const char*)g_rkT_hi + eb);
                        cp16(d + 3 * TILEB, (const char*)g_rkT_lo + eb);
                    }
                    CP_COMMIT();
                }
            }

#pragma unroll
            for (int mf = 0; mf < 2; mf++) {
#pragma unroll
                for (int nf = 0; nf < 8; nf++) {
                    const float* a = &accs[(mf * 8 + nf) * 4];
                    const int row = mbase + mf * 16 + (lane >> 2);
                    const int col = n0 + nbase + (nf >> 1) * 16 + (nf & 1) * 8 + (lane & 3) * 2;
                    float* p = g_rgp + ((size_t)ks * Bb + row) * G3 + col;
                    *(float2*)p = make_float2(a[0], a[1]);
                    *(float2*)(p + (size_t)8 * G3) = make_float2(a[2], a[3]);
                }
            }
            __syncthreads();
            if (tid == 0) {
                __threadfence();
                epoch++;
                atomicAdd(&g_bar, 1u);
                while (*(volatile unsigned*)&g_bar < epoch * GRID_GRU) { }
            }
            __syncthreads();
        }

        // ---------------- phase B: gates ----------------
        {
            const float* __restrict__ xgt = g_xg + (size_t)t * Bb * G3;
            const float* __restrict__ hprev = g_hs + (size_t)(t - 1) * Bb * Hh;
            float* __restrict__ hcur = g_hs + (size_t)t * Bb * Hh;
            for (int v = blockIdx.x * 256 + tid; v < (Bb * Hh) / 4; v += GRID_GRU * 256) {
                const int b = v >> 8;
                const int j = (v & 255) << 2;
                const size_t xb = (size_t)b * G3 + j;
                float4 xz = *(const float4*)(xgt + xb);
                float4 xr = *(const float4*)(xgt + xb + Hh);
                float4 xh = *(const float4*)(xgt + xb + 2 * Hh);
                float4 az = make_float4(0.f, 0.f, 0.f, 0.f);
                float4 ar = az, ah = az, hp = az;
                if (t > 0) {
#pragma unroll
                    for (int s = 0; s < NKS; s++) {
                        const float* rp = g_rgp + (size_t)s * Bb * G3 + xb;
                        float4 a0 = __ldcg((const float4*)(rp));
                        float4 a1 = __ldcg((const float4*)(rp + Hh));
                        float4 a2 = __ldcg((const float4*)(rp + 2 * Hh));
                        az.x += a0.x; az.y += a0.y; az.z += a0.z; az.w += a0.w;
                        ar.x += a1.x; ar.y += a1.y; ar.z += a1.z; ar.w += a1.w;
                        ah.x += a2.x; ah.y += a2.y; ah.z += a2.z; ah.w += a2.w;
                    }
                    hp = __ldcg((const float4*)(hprev + (size_t)b * Hh + j));
                }
                float4 bz = *(const float4*)(br + j);
                float4 brv = *(const float4*)(br + Hh + j);
                float4 bh = *(const float4*)(br + 2 * Hh + j);
                float4 o;
#define GATE1(C) { \
                float z = sig_(xz.C + az.C + bz.C); \
                float rg = sig_(xr.C + ar.C + brv.C); \
                float th = tanhf(xh.C + rg * (ah.C + bh.C)); \
                o.C = z * hp.C + (1.f - z) * th; }
                GATE1(x) GATE1(y) GATE1(z) GATE1(w)
#undef GATE1
                *(float4*)(hcur + (size_t)b * Hh + j) = o;
                __nv_bfloat16 h0 = __float2bfloat16(o.x);
                __nv_bfloat16 h1 = __float2bfloat16(o.y);
                __nv_bfloat16 h2 = __float2bfloat16(o.z);
                __nv_bfloat16 h3 = __float2bfloat16(o.w);
                union { __nv_bfloat16 bf[4]; uint2 u; } ph, pl;
                ph.bf[0] = h0; ph.bf[1] = h1; ph.bf[2] = h2; ph.bf[3] = h3;
                pl.bf[0] = __float2bfloat16(o.x - __bfloat162float(h0));
                pl.bf[1] = __float2bfloat16(o.y - __bfloat162float(h1));
                pl.bf[2] = __float2bfloat16(o.z - __bfloat162float(h2));
                pl.bf[3] = __float2bfloat16(o.w - __bfloat162float(h3));
                *(uint2*)(g_hhi + (size_t)b * Hh + j) = ph.u;
                *(uint2*)(g_hlo + (size_t)b * Hh + j) = pl.u;
            }
        }
        __syncthreads();
        if (tid == 0) {
            __threadfence();
            epoch++;
            atomicAdd(&g_bar, 1u);
            while (*(volatile unsigned*)&g_bar < epoch * GRID_GRU) { }
        }
        __syncthreads();
    }

    // ================= w1 post-phase: d = relu(hs @ w1 + b1) (fp32) ========
    for (int job = blockIdx.x; job < W1_JOBS; job += GRID_GRU) {
        const int wn0 = (job & 1) * 64;
        const int wm0 = (job >> 1) * 64;
        const int tx = tid & 15, ty = tid >> 4;
        const int a_row = tid >> 2, a_c4 = tid & 3;
        const int b_row = tid >> 4, b_c4 = tid & 15;
        const float* __restrict__ apt = g_hs + (size_t)(wm0 + a_row) * Hh;

        float acc[4][4];
#pragma unroll
        for (int i = 0; i < 4; i++)
#pragma unroll
            for (int j = 0; j < 4; j++) acc[i][j] = 0.f;

        for (int k0 = 0; k0 < Hh; k0 += 16) {
            float4 av = *reinterpret_cast<const float4*>(apt + k0 + a_c4 * 4);
            float4 bv = *reinterpret_cast<const float4*>(
                w1 + (size_t)(k0 + b_row) * Dd + wn0 + b_c4 * 4);
            W1As[a_c4 * 4 + 0][a_row] = av.x;
            W1As[a_c4 * 4 + 1][a_row] = av.y;
            W1As[a_c4 * 4 + 2][a_row] = av.z;
            W1As[a_c4 * 4 + 3][a_row] = av.w;
            *reinterpret_cast<float4*>(&W1Bs[b_row][b_c4 * 4]) = bv;
            __syncthreads();
#pragma unroll
            for (int kk = 0; kk < 16; kk++) {
                float4 a = *reinterpret_cast<const float4*>(&W1As[kk][ty * 4]);
                float4 b = *reinterpret_cast<const float4*>(&W1Bs[kk][tx * 4]);
                float aa[4] = {a.x, a.y, a.z, a.w};
                float bb[4] = {b.x, b.y, b.z, b.w};
#pragma unroll
                for (int i = 0; i < 4; i++)
#pragma unroll
                    for (int j = 0; j < 4; j++)
                        acc[i][j] = fmaf(aa[i], bb[j], acc[i][j]);
            }
            __syncthreads();
        }
#pragma unroll
        for (int i = 0; i < 4; i++) {
            int row = wm0 + ty * 4 + i;
            int col = wn0 + tx * 4;
            float4 o;
            o.x = fmaxf(acc[i][0] + b1[col + 0], 0.f);
            o.y = fmaxf(acc[i][1] + b1[col + 1], 0.f);
            o.z = fmaxf(acc[i][2] + b1[col + 2], 0.f);
            o.w = fmaxf(acc[i][3] + b1[col + 3], 0.f);
            union { __nv_bfloat16 bf[4]; uint2 u; } ph, pl;
            ph.bf[0] = __float2bfloat16(o.x);
            ph.bf[1] = __float2bfloat16(o.y);
            ph.bf[2] = __float2bfloat16(o.z);
            ph.bf[3] = __float2bfloat16(o.w);
            pl.bf[0] = __float2bfloat16(o.x - __bfloat162float(ph.bf[0]));
            pl.bf[1] = __float2bfloat16(o.y - __bfloat162float(ph.bf[1]));
            pl.bf[2] = __float2bfloat16(o.z - __bfloat162float(ph.bf[2]));
            pl.bf[3] = __float2bfloat16(o.w - __bfloat162float(ph.bf[3]));
            *(uint2*)(g_dhi + (size_t)row * Dd + col) = ph.u;
            *(uint2*)(g_dlo + (size_t)row * Dd + col) = pl.u;
        }
    }
    // grid barrier
    __syncthreads();
    if (tid == 0) {
        __threadfence();
        epoch++;
        atomicAdd(&g_bar, 1u);
        while (*(volatile unsigned*)&g_bar < epoch * GRID_GRU) { }
    }
    __syncthreads();

    // ================= w2 post-phase: logits = d @ w2T + b2 (mma) ==========
    for (int job = blockIdx.x; job < W2_JOBS; job += GRID_GRU) {
        const int wn0 = (job / 128) * 128;
        const int wm0 = (job % 128) * 128;

        float accs[64];
#pragma unroll
        for (int i = 0; i < 64; i++) accs[i] = 0.f;

#pragma unroll
        for (int c = 0; c < 2; c++) {
            const int kcur = c * 64;
            const uint32_t base = sb + c * BUFB;
#pragma unroll
            for (int i = 0; i < 4; i++) {
                const int row = lrow + 32 * i;
                const uint32_t d = base + row * ROWB + lg * 16;
                const size_t ea = ((size_t)(wm0 + row) * Dd + kcur + lg * 8) * 2;
                cp16(d,             (const char*)g_dhi + ea);
                cp16(d + TILEB,     (const char*)g_dlo + ea);
                const size_t eb = ((size_t)(wn0 + row) * Dd + kcur + lg * 8) * 2;
                cp16(d + 2 * TILEB, (const char*)g_w2T_hi + eb);
                cp16(d + 3 * TILEB, (const char*)g_w2T_lo + eb);
            }
            CP_COMMIT();
        }

#pragma unroll
        for (int c = 0; c < 2; c++) {
            if (c < 1) { CP_WAIT(1); } else { CP_WAIT(0); }
            __syncthreads();
            const uint32_t bufA = sb + (c & 1) * BUFB;
#pragma unroll
            for (int k = 0; k < 4; k++) {
                uint32_t ah[2][4], al[2][4];
#pragma unroll
                for (int mf = 0; mf < 2; mf++) {
                    const uint32_t ad = bufA + (mbase + mf * 16) * ROWB + k * 32 + aoff;
                    ldsm_x4(ah[mf], ad);
                    ldsm_x4(al[mf], ad + TILEB);
                }
#pragma unroll
                for (int nl = 0; nl < 4; nl++) {
                    const uint32_t bd = bufA + 2 * TILEB
                                      + (nbase + nl * 16) * ROWB + k * 32 + boff;
                    uint32_t bh[4], bl[4];
                    ldsm_x4(bh, bd);
                    ldsm_x4(bl, bd + TILEB);
#pragma unroll
                    for (int mf = 0; mf < 2; mf++) {
#pragma unroll
                        for (int h2 = 0; h2 < 2; h2++) {
                            float* a = &accs[(mf * 8 + nl * 2 + h2) * 4];
                            mma_16816(a, ah[mf], &bh[2 * h2]);
                            mma_16816(a, ah[mf], &bl[2 * h2]);
                            mma_16816(a, al[mf], &bh[2 * h2]);
                        }
                    }
                }
            }
            __syncthreads();
        }

#pragma unroll
        for (int mf = 0; mf < 2; mf++) {
#pragma unroll
            for (int nf = 0; nf < 8; nf++) {
                const float* a = &accs[(mf * 8 + nf) * 4];
                const int col = wn0 + nbase + (nf >> 1) * 16 + (nf & 1) * 8 + (lane & 3) * 2;
                if (col >= Vv) continue;
                float2 bv = *(const float2*)(b2 + col);
#pragma unroll
                for (int half = 0; half < 2; half++) {
                    const int r = wm0 + mbase + mf * 16 + (lane >> 2) + half * 8;
                    const int tt = r >> 7, b = r & 127;
                    *(float2*)(out + ((size_t)b * Tt + tt) * Vv + col) =
                        make_float2(a[2 * half + 0] + bv.x, a[2 * half + 1] + bv.y);
                }
            }
        }
    }
}

// ---------------------------------------------------------------------------
// softmax rows of 10000 with logits*50
// ---------------------------------------------------------------------------
__global__ __launch_bounds__(256) void k_softmax(float* __restrict__ out)
{
    float* __restrict__ p = out + (size_t)blockIdx.x * Vv;
    const int tid = threadIdx.x;
    float vals[40];
    float mx = -1e30f;
#pragma unroll
    for (int i = 0; i < 40; i++) {
        int idx = tid + (i << 8);
        if (idx < Vv) {
            float v = p[idx] * 50.0f;
            vals[i] = v;
            mx = fmaxf(mx, v);
        } else {
            vals[i] = -1e30f;
        }
    }
    __shared__ float redm[8];
    __shared__ float reds[8];
#pragma unroll
    for (int o = 16; o; o >>= 1) mx = fmaxf(mx, __shfl_xor_sync(0xffffffffu, mx, o));
    if ((tid & 31) == 0) redm[tid >> 5] = mx;
    __syncthreads();
    mx = redm[0];
#pragma unroll
    for (int w = 1; w < 8; w++) mx = fmaxf(mx, redm[w]);

    float s = 0.f;
#pragma unroll
    for (int i = 0; i < 40; i++) {
        int idx = tid + (i << 8);
        if (idx < Vv) {
            float e = expf(vals[i] - mx);
            vals[i] = e;
            s += e;
        }
    }
#pragma unroll
    for (int o = 16; o; o >>= 1) s += __shfl_xor_sync(0xffffffffu, s, o);
    if ((tid & 31) == 0) reds[tid >> 5] = s;
    __syncthreads();
    float tot = 0.f;
#pragma unroll
    for (int w = 0; w < 8; w++) tot += reds[w];
    float inv = 1.0f / tot;
#pragma unroll
    for (int i = 0; i < 40; i++) {
        int idx = tid + (i << 8);
        if (idx < Vv) p[idx] = vals[i] * inv;
    }
}

// ---------------------------------------------------------------------------
extern "C" void kernel_launch(void* const* d_in, const int* in_sizes, int n_in,
                              void* d_out, int out_size)
{
    const int*   tokens = (const int*)  d_in[0];
    const float* emb    = (const float*)d_in[1];
    const float* gk     = (const float*)d_in[2];
    const float* grk    = (const float*)d_in[3];
    const float* gbi    = (const float*)d_in[4];
    const float* gbr    = (const float*)d_in[5];
    const float* w1     = (const float*)d_in[6];
    const float* b1     = (const float*)d_in[7];
    const float* w2     = (const float*)d_in[8];
    const float* b2     = (const float*)d_in[9];
    float* out = (float*)d_out;

    cudaFuncSetAttribute(k_gru_mma, cudaFuncAttributeMaxDynamicSharedMemorySize, GRU_SMEM);

    dim3 blk(256);
    k_reset<<<1, 1>>>();
    k_rk_split<<<dim3(G3 / 32, Hh / 32), blk>>>(grk);
    k_gksplit<<<dim3(G3 / 32, Ee / 32), blk>>>(gk);
    k_w2split<<<dim3(VvPad / 32, Dd / 32), blk>>>(w2);
    k_xsplit<<<(MROWS * 64) / 256, blk>>>(tokens, emb);
    k_gru_mma<<<GRID_GRU, blk, GRU_SMEM>>>(gbr, gbi, w1, b1, b2, out);
    k_softmax<<<MROWS, blk>>>(out);
}

// round 15
// speedup vs baseline: 1.0880x; 1.0880x over previous
#include <cuda_runtime.h>
#include <cuda_bf16.h>
#include <math.h>
#include <stdint.h>

#define Bb 128
#define Tt 128
#define Vv 10000
#define VvPad 10112          // 79*128
#define Ee 256
#define Hh 1024
#define Dd 128
#define G3 3072              // 3*H
#define MROWS (Bb*Tt)        // 16384
#define NKS 6                // GRU k-splits: 192,192,192,192,128,128
#define NNT 24               // GRU n-tiles of 128
#define GRID_GRU (NKS*NNT)   // 144 CTAs, all co-resident
#define EMB_JOBS (24*128)    // 3072 embed tile-jobs
#define W1_JOBS  128         // w1 mma tile-jobs (128x128, N=128 single tile)
#define W2_JOBS  (79*128)    // 10112 w2 tile-jobs (128x128)

// ---------------- scratch (__device__ globals: allowed) --------------------
__device__ float g_xg[MROWS * G3];       // [T][B][3H] input-side preacts (incl bi)
__device__ float g_hs[MROWS * Hh];       // [T][B][H] fp32 (gate hprev)
__device__ float g_rgp[NKS * Bb * G3];   // recurrent matmul partials per k-split
__device__ __nv_bfloat16 g_rkT_hi[G3 * Hh];  // rk^T split hi  [n][k]
__device__ __nv_bfloat16 g_rkT_lo[G3 * Hh];  // rk^T split lo
__device__ __nv_bfloat16 g_hhi[Bb * Hh];     // h_t split hi [b][k] (GRU phase A)
__device__ __nv_bfloat16 g_hlo[Bb * Hh];     // h_t split lo
__device__ __nv_bfloat16 g_hshi[MROWS * Hh]; // per-step h split (w1 input)
__device__ __nv_bfloat16 g_hslo[MROWS * Hh];
__device__ __nv_bfloat16 g_w1T_hi[Dd * Hh];  // w1^T split [n=128][k=1024]
__device__ __nv_bfloat16 g_w1T_lo[Dd * Hh];
__device__ __nv_bfloat16 g_w2T_hi[VvPad * Dd]; // w2^T split, zero-padded rows
__device__ __nv_bfloat16 g_w2T_lo[VvPad * Dd];
__device__ __nv_bfloat16 g_dhi[MROWS * Dd];  // d = relu(hs@w1+b1) split hi
__device__ __nv_bfloat16 g_dlo[MROWS * Dd];  // split lo
__device__ __nv_bfloat16 g_gkT_hi[G3 * Ee];  // gru_k^T split [n][k]
__device__ __nv_bfloat16 g_gkT_lo[G3 * Ee];
__device__ __nv_bfloat16 g_xhi[MROWS * Ee];  // x = emb[tokens] split
__device__ __nv_bfloat16 g_xlo[MROWS * Ee];
__device__ unsigned g_bar;

__global__ void k_reset() { g_bar = 0u; }

// ---------------- PTX helpers ----------------------------------------------
__device__ __forceinline__ uint32_t smem_to_u32(const void* p) {
    uint32_t a;
    asm("{ .reg .u64 t; cvta.to.shared.u64 t, %1; cvt.u32.u64 %0, t; }"
        : "=r"(a) : "l"(p));
    return a;
}
__device__ __forceinline__ void ldsm_x4(uint32_t* r, uint32_t addr) {
    asm volatile("ldmatrix.sync.aligned.m8n8.x4.shared.b16 {%0,%1,%2,%3}, [%4];"
        : "=r"(r[0]), "=r"(r[1]), "=r"(r[2]), "=r"(r[3]) : "r"(addr));
}
__device__ __forceinline__ void mma_16816(float* d, const uint32_t* a, const uint32_t* b) {
    asm volatile("mma.sync.aligned.m16n8k16.row.col.f32.bf16.bf16.f32 "
        "{%0,%1,%2,%3}, {%4,%5,%6,%7}, {%8,%9}, {%0,%1,%2,%3};"
        : "+f"(d[0]), "+f"(d[1]), "+f"(d[2]), "+f"(d[3])
        : "r"(a[0]), "r"(a[1]), "r"(a[2]), "r"(a[3]), "r"(b[0]), "r"(b[1]));
}
__device__ __forceinline__ void cp16(uint32_t dst, const void* src) {
    asm volatile("cp.async.cg.shared.global [%0], [%1], 16;" :: "r"(dst), "l"(src));
}
#define CP_COMMIT() asm volatile("cp.async.commit_group;" ::: "memory")
#define CP_WAIT(n)  asm volatile("cp.async.wait_group %0;" :: "n"(n) : "memory")

__device__ __forceinline__ float sig_(float x) { return 1.f / (1.f + expf(-x)); }

// SMEM tile geometry: 128 rows x 64 bf16, rows padded to 72 bf16 = 144 B
#define ROWB 144
#define TILEB 18432          // 128*144
#define BUFB  (4*TILEB)      // Ah, Al, Bh, Bl
#define GRU_SMEM (2*BUFB)    // double buffered = 147456 B

// ---------------------------------------------------------------------------
// init: split + transpose rk [K=1024][N=3072] -> rkT hi/lo [N=3072][K=1024]
// ---------------------------------------------------------------------------
__global__ __launch_bounds__(256) void k_rk_split(const float* __restrict__ rk)
{
    __shared__ float tile[32][33];
    const int n0 = blockIdx.x * 32, k0 = blockIdx.y * 32;
    const int tx = threadIdx.x & 31, ty = threadIdx.x >> 5;  // ty 0..7
#pragma unroll
    for (int i = 0; i < 4; i++)
        tile[ty + 8 * i][tx] = rk[(size_t)(k0 + ty + 8 * i) * G3 + n0 + tx];
    __syncthreads();
#pragma unroll
    for (int i = 0; i < 4; i++) {
        int n = n0 + ty + 8 * i;
        float v = tile[tx][ty + 8 * i];
        __nv_bfloat16 hi = __float2bfloat16(v);
        __nv_bfloat16 lo = __float2bfloat16(v - __bfloat162float(hi));
        g_rkT_hi[(size_t)n * Hh + k0 + tx] = hi;
        g_rkT_lo[(size_t)n * Hh + k0 + tx] = lo;
    }
}

// ---------------------------------------------------------------------------
// init: split + transpose gk [K=256][N=3072] -> gkT hi/lo [N=3072][K=256]
// ---------------------------------------------------------------------------
__global__ __launch_bounds__(256) void k_gksplit(const float* __restrict__ gk)
{
    __shared__ float tile[32][33];
    const int n0 = blockIdx.x * 32, k0 = blockIdx.y * 32;
    const int tx = threadIdx.x & 31, ty = threadIdx.x >> 5;
#pragma unroll
    for (int i = 0; i < 4; i++)
        tile[ty + 8 * i][tx] = gk[(size_t)(k0 + ty + 8 * i) * G3 + n0 + tx];
    __syncthreads();
#pragma unroll
    for (int i = 0; i < 4; i++) {
        int n = n0 + ty + 8 * i;
        float v = tile[tx][ty + 8 * i];
        __nv_bfloat16 hi = __float2bfloat16(v);
        __nv_bfloat16 lo = __float2bfloat16(v - __bfloat162float(hi));
        g_gkT_hi[(size_t)n * Ee + k0 + tx] = hi;
        g_gkT_lo[(size_t)n * Ee + k0 + tx] = lo;
    }
}

// ---------------------------------------------------------------------------
// init: split + transpose w1 [K=1024][N=128] -> w1T hi/lo [128][1024]
// grid (Dd/32, Hh/32)
// ---------------------------------------------------------------------------
__global__ __launch_bounds__(256) void k_w1split(const float* __restrict__ w1)
{
    __shared__ float tile[32][33];
    const int n0 = blockIdx.x * 32, k0 = blockIdx.y * 32;
    const int tx = threadIdx.x & 31, ty = threadIdx.x >> 5;
#pragma unroll
    for (int i = 0; i < 4; i++)
        tile[ty + 8 * i][tx] = w1[(size_t)(k0 + ty + 8 * i) * Dd + n0 + tx];
    __syncthreads();
#pragma unroll
    for (int i = 0; i < 4; i++) {
        int n = n0 + ty + 8 * i;
        float v = tile[tx][ty + 8 * i];
        __nv_bfloat16 hi = __float2bfloat16(v);
        __nv_bfloat16 lo = __float2bfloat16(v - __bfloat162float(hi));
        g_w1T_hi[(size_t)n * Hh + k0 + tx] = hi;
        g_w1T_lo[(size_t)n * Hh + k0 + tx] = lo;
    }
}

// ---------------------------------------------------------------------------
// init: gather + split x = emb[tokens]  (row r = t*B+b)
// ---------------------------------------------------------------------------
__global__ __launch_bounds__(256) void k_xsplit(
    const int* __restrict__ tokens, const float* __restrict__ emb)
{
    int idx = blockIdx.x * 256 + threadIdx.x;   // float4 index over MROWS*64
    int r = idx >> 6, c4 = idx & 63;
    int tok = tokens[(r & 127) * Tt + (r >> 7)];
    float4 v = reinterpret_cast<const float4*>(emb)[(size_t)tok * 64 + c4];
    union { __nv_bfloat16 bf[4]; uint2 u; } ph, pl;
    ph.bf[0] = __float2bfloat16(v.x); ph.bf[1] = __float2bfloat16(v.y);
    ph.bf[2] = __float2bfloat16(v.z); ph.bf[3] = __float2bfloat16(v.w);
    pl.bf[0] = __float2bfloat16(v.x - __bfloat162float(ph.bf[0]));
    pl.bf[1] = __float2bfloat16(v.y - __bfloat162float(ph.bf[1]));
    pl.bf[2] = __float2bfloat16(v.z - __bfloat162float(ph.bf[2]));
    pl.bf[3] = __float2bfloat16(v.w - __bfloat162float(ph.bf[3]));
    *(uint2*)(g_xhi + (size_t)r * Ee + c4 * 4) = ph.u;
    *(uint2*)(g_xlo + (size_t)r * Ee + c4 * 4) = pl.u;
}

// ---------------------------------------------------------------------------
// init: split + transpose w2 [Dd=128][Vv] -> w2T hi/lo [VvPad][Dd], zero-pad
// ---------------------------------------------------------------------------
__global__ __launch_bounds__(256) void k_w2split(const float* __restrict__ w2)
{
    __shared__ float tile[32][33];
    const int n0 = blockIdx.x * 32, k0 = blockIdx.y * 32;
    const int tx = threadIdx.x & 31, ty = threadIdx.x >> 5;
#pragma unroll
    for (int i = 0; i < 4; i++) {
        int c = n0 + tx;
        tile[ty + 8 * i][tx] =
            (c < Vv) ? w2[(size_t)(k0 + ty + 8 * i) * Vv + c] : 0.f;
    }
    __syncthreads();
#pragma unroll
    for (int i = 0; i < 4; i++) {
        int n = n0 + ty + 8 * i;
        float v = tile[tx][ty + 8 * i];
        __nv_bfloat16 hi = __float2bfloat16(v);
        __nv_bfloat16 lo = __float2bfloat16(v - __bfloat162float(hi));
        g_w2T_hi[(size_t)n * Dd + k0 + tx] = hi;
        g_w2T_lo[(size_t)n * Dd + k0 + tx] = lo;
    }
}

// ---------------------------------------------------------------------------
// Persistent mega-kernel: embed -> barrier -> GRU loop -> w1(mma) -> barrier
// -> w2(mma).
// ---------------------------------------------------------------------------
__global__ __launch_bounds__(256, 1) void k_gru_mma(
    const float* __restrict__ br, const float* __restrict__ bi,
    const float* __restrict__ b1, const float* __restrict__ b2,
    float* __restrict__ out)
{
    extern __shared__ char smem[];
    const uint32_t sb = smem_to_u32(smem);
    const int tid = threadIdx.x;
    const int lane = tid & 31;
    const int wid = tid >> 5;
    const int ntile = blockIdx.x % NNT;
    const int ks    = blockIdx.x / NNT;      // 0..5
    const int n0    = ntile * 128;
    const int kbase = (ks < 4) ? ks * 192 : 768 + (ks - 4) * 128;
    const int nch   = (ks < 4) ? 3 : 2;      // chunks of 64 k
    const int mbase = (wid & 3) * 32;        // warp M rows
    const int nbase = (wid >> 2) * 64;       // warp N cols within tile

    const int lrow = tid >> 3;
    const int lg   = tid & 7;
    const uint32_t aoff = (uint32_t)((lane & 15) * ROWB + ((lane >> 4) & 1) * 16);
    const uint32_t boff = (uint32_t)((((lane & 7) + ((lane >> 4) & 1) * 8)) * ROWB
                                     + ((lane >> 3) & 1) * 16);

    unsigned epoch = 0;

    // ================= embed pre-phase: xg = x @ gkT + bi =================
    for (int job = blockIdx.x; job < EMB_JOBS; job += GRID_GRU) {
        const int em0 = (job & 127) * 128;   // m-tile
        const int en0 = (job >> 7) * 128;    // n-tile (0..23)

        float accs[64];
#pragma unroll
        for (int i = 0; i < 64; i++) accs[i] = 0.f;

#pragma unroll
        for (int c = 0; c < 2; c++) {
            const int kcur = c * 64;
            const uint32_t base = sb + c * BUFB;
#pragma unroll
            for (int i = 0; i < 4; i++) {
                const int row = lrow + 32 * i;
                const uint32_t d = base + row * ROWB + lg * 16;
                const size_t ea = ((size_t)(em0 + row) * Ee + kcur + lg * 8) * 2;
                cp16(d,             (const char*)g_xhi + ea);
                cp16(d + TILEB,     (const char*)g_xlo + ea);
                const size_t eb = ((size_t)(en0 + row) * Ee + kcur + lg * 8) * 2;
                cp16(d + 2 * TILEB, (const char*)g_gkT_hi + eb);
                cp16(d + 3 * TILEB, (const char*)g_gkT_lo + eb);
            }
            CP_COMMIT();
        }

        for (int c = 0; c < 4; c++) {
            if (c < 3) { CP_WAIT(1); } else { CP_WAIT(0); }
            __syncthreads();
            const uint32_t bufA = sb + (c & 1) * BUFB;
#pragma unroll
            for (int k = 0; k < 4; k++) {
                uint32_t ah[2][4], al[2][4];
#pragma unroll
                for (int mf = 0; mf < 2; mf++) {
                    const uint32_t ad = bufA + (mbase + mf * 16) * ROWB + k * 32 + aoff;
                    ldsm_x4(ah[mf], ad);
                    ldsm_x4(al[mf], ad + TILEB);
                }
#pragma unroll
                for (int nl = 0; nl < 4; nl++) {
                    const uint32_t bd = bufA + 2 * TILEB
                                      + (nbase + nl * 16) * ROWB + k * 32 + boff;
                    uint32_t bh[4], bl[4];
                    ldsm_x4(bh, bd);
                    ldsm_x4(bl, bd + TILEB);
#pragma unroll
                    for (int mf = 0; mf < 2; mf++) {
#pragma unroll
                        for (int h2 = 0; h2 < 2; h2++) {
                            float* a = &accs[(mf * 8 + nl * 2 + h2) * 4];
                            mma_16816(a, ah[mf], &bh[2 * h2]);
                            mma_16816(a, ah[mf], &bl[2 * h2]);
                            mma_16816(a, al[mf], &bh[2 * h2]);
                        }
                    }
                }
            }
            __syncthreads();
            if (c + 2 < 4) {
                const int cc = c + 2;
                const int kcur = cc * 64;
                const uint32_t base = sb + (cc & 1) * BUFB;
#pragma unroll
                for (int i = 0; i < 4; i++) {
                    const int row = lrow + 32 * i;
                    const uint32_t d = base + row * ROWB + lg * 16;
                    const size_t ea = ((size_t)(em0 + row) * Ee + kcur + lg * 8) * 2;
                    cp16(d,             (const char*)g_xhi + ea);
                    cp16(d + TILEB,     (const char*)g_xlo + ea);
                    const size_t eb = ((size_t)(en0 + row) * Ee + kcur + lg * 8) * 2;
                    cp16(d + 2 * TILEB, (const char*)g_gkT_hi + eb);
                    cp16(d + 3 * TILEB, (const char*)g_gkT_lo + eb);
                }
                CP_COMMIT();
            }
        }

#pragma unroll
        for (int mf = 0; mf < 2; mf++) {
#pragma unroll
            for (int nf = 0; nf < 8; nf++) {
                const float* a = &accs[(mf * 8 + nf) * 4];
                const int col = en0 + nbase + (nf >> 1) * 16 + (nf & 1) * 8 + (lane & 3) * 2;
                float2 bv = *(const float2*)(bi + col);
#pragma unroll
                for (int half = 0; half < 2; half++) {
                    const int r = em0 + mbase + mf * 16 + (lane >> 2) + half * 8;
                    *(float2*)(g_xg + (size_t)r * G3 + col) =
                        make_float2(a[2 * half + 0] + bv.x, a[2 * half + 1] + bv.y);
                }
            }
        }
    }
    __syncthreads();
    if (tid == 0) {
        __threadfence();
        epoch++;
        atomicAdd(&g_bar, 1u);
        while (*(volatile unsigned*)&g_bar < epoch * GRID_GRU) { }
    }
    __syncthreads();

    // ================= GRU time loop =================
    for (int t = 0; t < Tt; t++) {
        if (t > 0) {
            float accs[64];
#pragma unroll
            for (int i = 0; i < 64; i++) accs[i] = 0.f;

#pragma unroll
            for (int c = 0; c < 2; c++) {
                const int kcur = kbase + c * 64;
                const uint32_t base = sb + c * BUFB;
#pragma unroll
                for (int i = 0; i < 4; i++) {
                    const int row = lrow + 32 * i;
                    const uint32_t d = base + row * ROWB + lg * 16;
                    const size_t ea = ((size_t)row * Hh + kcur + lg * 8) * 2;
                    cp16(d,             (const char*)g_hhi + ea);
                    cp16(d + TILEB,     (const char*)g_hlo + ea);
                    const size_t eb = ((size_t)(n0 + row) * Hh + kcur + lg * 8) * 2;
                    cp16(d + 2 * TILEB, (const char*)g_rkT_hi + eb);
                    cp16(d + 3 * TILEB, (const char*)g_rkT_lo + eb);
                }
                CP_COMMIT();
            }

            for (int c = 0; c < nch; c++) {
                if (c < nch - 1) { CP_WAIT(1); } else { CP_WAIT(0); }
                __syncthreads();
                const uint32_t bufA = sb + (c & 1) * BUFB;
#pragma unroll
                for (int k = 0; k < 4; k++) {
                    uint32_t ah[2][4], al[2][4];
#pragma unroll
                    for (int mf = 0; mf < 2; mf++) {
                        const uint32_t ad = bufA + (mbase + mf * 16) * ROWB + k * 32 + aoff;
                        ldsm_x4(ah[mf], ad);
                        ldsm_x4(al[mf], ad + TILEB);
                    }
#pragma unroll
                    for (int nl = 0; nl < 4; nl++) {
                        const uint32_t bd = bufA + 2 * TILEB
                                          + (nbase + nl * 16) * ROWB + k * 32 + boff;
                        uint32_t bh[4], bl[4];
                        ldsm_x4(bh, bd);
                        ldsm_x4(bl, bd + TILEB);
#pragma unroll
                        for (int mf = 0; mf < 2; mf++) {
#pragma unroll
                            for (int h2 = 0; h2 < 2; h2++) {
                                float* a = &accs[(mf * 8 + nl * 2 + h2) * 4];
                                mma_16816(a, ah[mf], &bh[2 * h2]);
                                mma_16816(a, ah[mf], &bl[2 * h2]);
                                mma_16816(a, al[mf], &bh[2 * h2]);
                            }
                        }
                    }
                }
                __syncthreads();
                if (c + 2 < nch) {
                    const int cc = c + 2;
                    const int kcur = kbase + cc * 64;
                    const uint32_t base = sb + (cc & 1) * BUFB;
#pragma unroll
                    for (int i = 0; i < 4; i++) {
                        const int row = lrow + 32 * i;
                        const uint32_t d = base + row * ROWB + lg * 16;
                        const size_t ea = ((size_t)row * Hh + kcur + lg * 8) * 2;
                        cp16(d,             (const char*)g_hhi + ea);
                        cp16(d + TILEB,     (const char*)g_hlo + ea);
                        const size_t eb = ((size_t)(n0 + row) * Hh + kcur + lg * 8) * 2;
                        cp16(d + 2 * TILEB, (const char*)g_rkT_hi + eb);
                        cp16(d + 3 * TILEB, (const char*)g_rkT_lo + eb);
                    }
                    CP_COMMIT();
                }
            }

#pragma unroll
            for (int mf = 0; mf < 2; mf++) {
#pragma unroll
                for (int nf = 0; nf < 8; nf++) {
                    const float* a = &accs[(mf * 8 + nf) * 4];
                    const int row = mbase + mf * 16 + (lane >> 2);
                    const int col = n0 + nbase + (nf >> 1) * 16 + (nf & 1) * 8 + (lane & 3) * 2;
                    float* p = g_rgp + ((size_t)ks * Bb + row) * G3 + col;
                    *(float2*)p = make_float2(a[0], a[1]);
                    *(float2*)(p + (size_t)8 * G3) = make_float2(a[2], a[3]);
                }
            }
            __syncthreads();
            if (tid == 0) {
                __threadfence();
                epoch++;
                atomicAdd(&g_bar, 1u);
                while (*(volatile unsigned*)&g_bar < epoch * GRID_GRU) { }
            }
            __syncthreads();
        }

        // ---------------- phase B: gates ----------------
        {
            const float* __restrict__ xgt = g_xg + (size_t)t * Bb * G3;
            const float* __restrict__ hprev = g_hs + (size_t)(t - 1) * Bb * Hh;
            float* __restrict__ hcur = g_hs + (size_t)t * Bb * Hh;
            __nv_bfloat16* __restrict__ shhi = g_hshi + (size_t)t * Bb * Hh;
            __nv_bfloat16* __restrict__ shlo = g_hslo + (size_t)t * Bb * Hh;
            for (int v = blockIdx.x * 256 + tid; v < (Bb * Hh) / 4; v += GRID_GRU * 256) {
                const int b = v >> 8;
                const int j = (v & 255) << 2;
                const size_t xb = (size_t)b * G3 + j;
                float4 xz = *(const float4*)(xgt + xb);
                float4 xr = *(const float4*)(xgt + xb + Hh);
                float4 xh = *(const float4*)(xgt + xb + 2 * Hh);
                float4 az = make_float4(0.f, 0.f, 0.f, 0.f);
                float4 ar = az, ah = az, hp = az;
                if (t > 0) {
#pragma unroll
                    for (int s = 0; s < NKS; s++) {
                        const float* rp = g_rgp + (size_t)s * Bb * G3 + xb;
                        float4 a0 = __ldcg((const float4*)(rp));
                        float4 a1 = __ldcg((const float4*)(rp + Hh));
                        float4 a2 = __ldcg((const float4*)(rp + 2 * Hh));
                        az.x += a0.x; az.y += a0.y; az.z += a0.z; az.w += a0.w;
                        ar.x += a1.x; ar.y += a1.y; ar.z += a1.z; ar.w += a1.w;
                        ah.x += a2.x; ah.y += a2.y; ah.z += a2.z; ah.w += a2.w;
                    }
                    hp = __ldcg((const float4*)(hprev + (size_t)b * Hh + j));
                }
                float4 bz = *(const float4*)(br + j);
                float4 brv = *(const float4*)(br + Hh + j);
                float4 bh = *(const float4*)(br + 2 * Hh + j);
                float4 o;
#define GATE1(C) { \
                float z = sig_(xz.C + az.C + bz.C); \
                float rg = sig_(xr.C + ar.C + brv.C); \
                float th = tanhf(xh.C + rg * (ah.C + bh.C)); \
                o.C = z * hp.C + (1.f - z) * th; }
                GATE1(x) GATE1(y) GATE1(z) GATE1(w)
#undef GATE1
                *(float4*)(hcur + (size_t)b * Hh + j) = o;
                __nv_bfloat16 h0 = __float2bfloat16(o.x);
                __nv_bfloat16 h1 = __float2bfloat16(o.y);
                __nv_bfloat16 h2 = __float2bfloat16(o.z);
                __nv_bfloat16 h3 = __float2bfloat16(o.w);
                union { __nv_bfloat16 bf[4]; uint2 u; } ph, pl;
                ph.bf[0] = h0; ph.bf[1] = h1; ph.bf[2] = h2; ph.bf[3] = h3;
                pl.bf[0] = __float2bfloat16(o.x - __bfloat162float(h0));
                pl.bf[1] = __float2bfloat16(o.y - __bfloat162float(h1));
                pl.bf[2] = __float2bfloat16(o.z - __bfloat162float(h2));
                pl.bf[3] = __float2bfloat16(o.w - __bfloat162float(h3));
                *(uint2*)(g_hhi + (size_t)b * Hh + j) = ph.u;
                *(uint2*)(g_hlo + (size_t)b * Hh + j) = pl.u;
                *(uint2*)(shhi + (size_t)b * Hh + j) = ph.u;
                *(uint2*)(shlo + (size_t)b * Hh + j) = pl.u;
            }
        }
        __syncthreads();
        if (tid == 0) {
            __threadfence();
            epoch++;
            atomicAdd(&g_bar, 1u);
            while (*(volatile unsigned*)&g_bar < epoch * GRID_GRU) { }
        }
        __syncthreads();
    }

    // ================= w1 post-phase: d = relu(hs @ w1T + b1) (mma) ========
    for (int job = blockIdx.x; job < W1_JOBS; job += GRID_GRU) {
        const int wm0 = job * 128;

        float accs[64];
#pragma unroll
        for (int i = 0; i < 64; i++) accs[i] = 0.f;

#pragma unroll
        for (int c = 0; c < 2; c++) {
            const int kcur = c * 64;
            const uint32_t base = sb + c * BUFB;
#pragma unroll
            for (int i = 0; i < 4; i++) {
                const int row = lrow + 32 * i;
                const uint32_t d = base + row * ROWB + lg * 16;
                const size_t ea = ((size_t)(wm0 + row) * Hh + kcur + lg * 8) * 2;
                cp16(d,             (const char*)g_hshi + ea);
                cp16(d + TILEB,     (const char*)g_hslo + ea);
                const size_t eb = ((size_t)row * Hh + kcur + lg * 8) * 2;
                cp16(d + 2 * TILEB, (const char*)g_w1T_hi + eb);
                cp16(d + 3 * TILEB, (const char*)g_w1T_lo + eb);
            }
            CP_COMMIT();
        }

        for (int c = 0; c < 16; c++) {
            if (c < 15) { CP_WAIT(1); } else { CP_WAIT(0); }
            __syncthreads();
            const uint32_t bufA = sb + (c & 1) * BUFB;
#pragma unroll
            for (int k = 0; k < 4; k++) {
                uint32_t ah[2][4], al[2][4];
#pragma unroll
                for (int mf = 0; mf < 2; mf++) {
                    const uint32_t ad = bufA + (mbase + mf * 16) * ROWB + k * 32 + aoff;
                    ldsm_x4(ah[mf], ad);
                    ldsm_x4(al[mf], ad + TILEB);
                }
#pragma unroll
                for (int nl = 0; nl < 4; nl++) {
                    const uint32_t bd = bufA + 2 * TILEB
                                      + (nbase + nl * 16) * ROWB + k * 32 + boff;
                    uint32_t bh[4], bl[4];
                    ldsm_x4(bh, bd);
                    ldsm_x4(bl, bd + TILEB);
#pragma unroll
                    for (int mf = 0; mf < 2; mf++) {
#pragma unroll
                        for (int h2 = 0; h2 < 2; h2++) {
                            float* a = &accs[(mf * 8 + nl * 2 + h2) * 4];
                            mma_16816(a, ah[mf], &bh[2 * h2]);
                            mma_16816(a, ah[mf], &bl[2 * h2]);
                            mma_16816(a, al[mf], &bh[2 * h2]);
                        }
                    }
                }
            }
            __syncthreads();
            if (c + 2 < 16) {
                const int cc = c + 2;
                const int kcur = cc * 64;
                const uint32_t base = sb + (cc & 1) * BUFB;
#pragma unroll
                for (int i = 0; i < 4; i++) {
                    const int row = lrow + 32 * i;
                    const uint32_t d = base + row * ROWB + lg * 16;
                    const size_t ea = ((size_t)(wm0 + row) * Hh + kcur + lg * 8) * 2;
                    cp16(d,             (const char*)g_hshi + ea);
                    cp16(d + TILEB,     (const char*)g_hslo + ea);
                    const size_t eb = ((size_t)row * Hh + kcur + lg * 8) * 2;
                    cp16(d + 2 * TILEB, (const char*)g_w1T_hi + eb);
                    cp16(d + 3 * TILEB, (const char*)g_w1T_lo + eb);
                }
                CP_COMMIT();
            }
        }

        // epilogue: relu(acc + b1) -> split g_dhi/g_dlo (n0 = 0)
#pragma unroll
        for (int mf = 0; mf < 2; mf++) {
#pragma unroll
            for (int nf = 0; nf < 8; nf++) {
                const float* a = &accs[(mf * 8 + nf) * 4];
                const int col = nbase + (nf >> 1) * 16 + (nf & 1) * 8 + (lane & 3) * 2;
                float2 bv = *(const float2*)(b1 + col);
#pragma unroll
                for (int half = 0; half < 2; half++) {
                    const int r = wm0 + mbase + mf * 16 + (lane >> 2) + half * 8;
                    float v0 = fmaxf(a[2 * half + 0] + bv.x, 0.f);
                    float v1 = fmaxf(a[2 * half + 1] + bv.y, 0.f);
                    union { __nv_bfloat16 bf[2]; uint32_t u; } ph, pl;
                    ph.bf[0] = __float2bfloat16(v0);
                    ph.bf[1] = __float2bfloat16(v1);
                    pl.bf[0] = __float2bfloat16(v0 - __bfloat162float(ph.bf[0]));
                    pl.bf[1] = __float2bfloat16(v1 - __bfloat162float(ph.bf[1]));
                    *(uint32_t*)(g_dhi + (size_t)r * Dd + col) = ph.u;
                    *(uint32_t*)(g_dlo + (size_t)r * Dd + col) = pl.u;
                }
            }
        }
    }
    __syncthreads();
    if (tid == 0) {
        __threadfence();
        epoch++;
        atomicAdd(&g_bar, 1u);
        while (*(volatile unsigned*)&g_bar < epoch * GRID_GRU) { }
    }
    __syncthreads();

    // ================= w2 post-phase: logits = d @ w2T + b2 (mma) ==========
    for (int job = blockIdx.x; job < W2_JOBS; job += GRID_GRU) {
        const int wn0 = (job / 128) * 128;
        const int wm0 = (job % 128) * 128;

        float accs[64];
#pragma unroll
        for (int i = 0; i < 64; i++) accs[i] = 0.f;

#pragma unroll
        for (int c = 0; c < 2; c++) {
            const int kcur = c * 64;
            const uint32_t base = sb + c * BUFB;
#pragma unroll
            for (int i = 0; i < 4; i++) {
                const int row = lrow + 32 * i;
                const uint32_t d = base + row * ROWB + lg * 16;
                const size_t ea = ((size_t)(wm0 + row) * Dd + kcur + lg * 8) * 2;
                cp16(d,             (const char*)g_dhi + ea);
                cp16(d + TILEB,     (const char*)g_dlo + ea);
                const size_t eb = ((size_t)(wn0 + row) * Dd + kcur + lg * 8) * 2;
                cp16(d + 2 * TILEB, (const char*)g_w2T_hi + eb);
                cp16(d + 3 * TILEB, (const char*)g_w2T_lo + eb);
            }
            CP_COMMIT();
        }

#pragma unroll
        for (int c = 0; c < 2; c++) {
            if (c < 1) { CP_WAIT(1); } else { CP_WAIT(0); }
            __syncthreads();
            const uint32_t bufA = sb + (c & 1) * BUFB;
#pragma unroll
            for (int k = 0; k < 4; k++) {
                uint32_t ah[2][4], al[2][4];
#pragma unroll
                for (int mf = 0; mf < 2; mf++) {
                    const uint32_t ad = bufA + (mbase + mf * 16) * ROWB + k * 32 + aoff;
                    ldsm_x4(ah[mf], ad);
                    ldsm_x4(al[mf], ad + TILEB);
                }
#pragma unroll
                for (int nl = 0; nl < 4; nl++) {
                    const uint32_t bd = bufA + 2 * TILEB
                                      + (nbase + nl * 16) * ROWB + k * 32 + boff;
                    uint32_t bh[4], bl[4];
                    ldsm_x4(bh, bd);
                    ldsm_x4(bl, bd + TILEB);
#pragma unroll
                    for (int mf = 0; mf < 2; mf++) {
#pragma unroll
                        for (int h2 = 0; h2 < 2; h2++) {
                            float* a = &accs[(mf * 8 + nl * 2 + h2) * 4];
                            mma_16816(a, ah[mf], &bh[2 * h2]);
                            mma_16816(a, ah[mf], &bl[2 * h2]);
                            mma_16816(a, al[mf], &bh[2 * h2]);
                        }
                    }
                }
            }
            __syncthreads();
        }

#pragma unroll
        for (int mf = 0; mf < 2; mf++) {
#pragma unroll
            for (int nf = 0; nf < 8; nf++) {
                const float* a = &accs[(mf * 8 + nf) * 4];
                const int col = wn0 + nbase + (nf >> 1) * 16 + (nf & 1) * 8 + (lane & 3) * 2;
                if (col >= Vv) continue;
                float2 bv = *(const float2*)(b2 + col);
#pragma unroll
                for (int half = 0; half < 2; half++) {
                    const int r = wm0 + mbase + mf * 16 + (lane >> 2) + half * 8;
                    const int tt = r >> 7, b = r & 127;
                    *(float2*)(out + ((size_t)b * Tt + tt) * Vv + col) =
                        make_float2(a[2 * half + 0] + bv.x, a[2 * half + 1] + bv.y);
                }
            }
        }
    }
}

// ---------------------------------------------------------------------------
// softmax rows of 10000 with logits*50
// ---------------------------------------------------------------------------
__global__ __launch_bounds__(256) void k_softmax(float* __restrict__ out)
{
    float* __restrict__ p = out + (size_t)blockIdx.x * Vv;
    const int tid = threadIdx.x;
    float vals[40];
    float mx = -1e30f;
#pragma unroll
    for (int i = 0; i < 40; i++) {
        int idx = tid + (i << 8);
        if (idx < Vv) {
            float v = p[idx] * 50.0f;
            vals[i] = v;
            mx = fmaxf(mx, v);
        } else {
            vals[i] = -1e30f;
        }
    }
    __shared__ float redm[8];
    __shared__ float reds[8];
#pragma unroll
    for (int o = 16; o; o >>= 1) mx = fmaxf(mx, __shfl_xor_sync(0xffffffffu, mx, o));
    if ((tid & 31) == 0) redm[tid >> 5] = mx;
    __syncthreads();
    mx = redm[0];
#pragma unroll
    for (int w = 1; w < 8; w++) mx = fmaxf(mx, redm[w]);

    float s = 0.f;
#pragma unroll
    for (int i = 0; i < 40; i++) {
        int idx = tid + (i << 8);
        if (idx < Vv) {
            float e = expf(vals[i] - mx);
            vals[i] = e;
            s += e;
        }
    }
#pragma unroll
    for (int o = 16; o; o >>= 1) s += __shfl_xor_sync(0xffffffffu, s, o);
    if ((tid & 31) == 0) reds[tid >> 5] = s;
    __syncthreads();
    float tot = 0.f;
#pragma unroll
    for (int w = 0; w < 8; w++) tot += reds[w];
    float inv = 1.0f / tot;
#pragma unroll
    for (int i = 0; i < 40; i++) {
        int idx = tid + (i << 8);
        if (idx < Vv) p[idx] = vals[i] * inv;
    }
}

// ---------------------------------------------------------------------------
extern "C" void kernel_launch(void* const* d_in, const int* in_sizes, int n_in,
                              void* d_out, int out_size)
{
    const int*   tokens = (const int*)  d_in[0];
    const float* emb    = (const float*)d_in[1];
    const float* gk     = (const float*)d_in[2];
    const float* grk    = (const float*)d_in[3];
    const float* gbi    = (const float*)d_in[4];
    const float* gbr    = (const float*)d_in[5];
    const float* w1     = (const float*)d_in[6];
    const float* b1     = (const float*)d_in[7];
    const float* w2     = (const float*)d_in[8];
    const float* b2     = (const float*)d_in[9];
    float* out = (float*)d_out;

    cudaFuncSetAttribute(k_gru_mma, cudaFuncAttributeMaxDynamicSharedMemorySize, GRU_SMEM);

    dim3 blk(256);
    k_reset<<<1, 1>>>();
    k_rk_split<<<dim3(G3 / 32, Hh / 32), blk>>>(grk);
    k_gksplit<<<dim3(G3 / 32, Ee / 32), blk>>>(gk);
    k_w1split<<<dim3(Dd / 32, Hh / 32), blk>>>(w1);
    k_w2split<<<dim3(VvPad / 32, Dd / 32), blk>>>(w2);
    k_xsplit<<<(MROWS * 64) / 256, blk>>>(tokens, emb);
    k_gru_mma<<<GRID_GRU, blk, GRU_SMEM>>>(gbr, gbi, b1, b2, out);
    k_softmax<<<MROWS, blk>>>(out);
}